// round 13
// baseline (speedup 1.0000x reference)
#include <cuda_runtime.h>

#define NB 8
#define NV 256
#define ND 64
#define NH 128
#define NI 32
#define NT 50
#define ROWS 16
#define XS 20
#define NTHR 512
#define GRID 128
#define CLUSTER 16

#define WORK0 0
#define WORK1 4096
#define W_IN  8192
#define W_H0  16384
#define W_H1  32768
#define W_OUT 49152
#define SM_FLOATS 57344
#define G_WR  16384
#define G_WZ  (16384 + 6144)
#define G_WG  (16384 + 12288)
#define G_WO  (16384 + 18432)

__device__ __forceinline__ float fast_tanh(float x) {
    float e = __expf(-2.0f * fabsf(x));
    float t = __fdividef(1.0f - e, 1.0f + e);
    return copysignf(t, x);
}
__device__ __forceinline__ float fast_sig(float x) {
    return __fdividef(1.0f, 1.0f + __expf(-x));
}
__device__ __forceinline__ void cluster_barrier() {
    __syncthreads();
    __threadfence();
    asm volatile("barrier.cluster.arrive.aligned;" ::: "memory");
    asm volatile("barrier.cluster.wait.aligned;" ::: "memory");
}
__device__ __forceinline__ void smcopy(float* dst, const float* src, int nfloats, int t) {
    float4* d4 = (float4*)dst;
    const float4* s4 = (const float4*)src;
    int n4 = nfloats >> 2;
    for (int i = t; i < n4; i += NTHR) d4[i] = s4[i];
}

// hidden layer Kout=128, 512 threads: tile 4r x 2c, k-split 2 ways.
// xin/xout [k][r] stride XS. Partials combined in xout via one extra sync.
template <int KIN>
__device__ void layer128(int t, const float* W, const float* __restrict__ bias,
                         const float* xin, float* xout) {
    const int c2 = (t & 63) * 2;
    const int r4 = ((t >> 6) & 3) * 4;
    const int kk = t >> 8;
    const int kh = KIN >> 1;
    float a[8] = {0.f, 0.f, 0.f, 0.f, 0.f, 0.f, 0.f, 0.f};
    const float* xp = xin + kk * kh * XS + r4;
    const float* wp = W + kk * kh * NH + c2;
#pragma unroll 4
    for (int k = 0; k < kh; k++) {
        float4 xv = *(const float4*)xp;
        float2 wv = *(const float2*)wp;
        xp += XS; wp += NH;
        a[0] += xv.x * wv.x; a[1] += xv.x * wv.y;
        a[2] += xv.y * wv.x; a[3] += xv.y * wv.y;
        a[4] += xv.z * wv.x; a[5] += xv.z * wv.y;
        a[6] += xv.w * wv.x; a[7] += xv.w * wv.y;
    }
    if (kk == 0) {
#pragma unroll
        for (int j = 0; j < 4; j++) {
            xout[c2 * XS + r4 + j] = a[2 * j];
            xout[(c2 + 1) * XS + r4 + j] = a[2 * j + 1];
        }
    }
    __syncthreads();
    if (kk == 1) {
        float b0 = __ldg(bias + c2), b1 = __ldg(bias + c2 + 1);
#pragma unroll
        for (int j = 0; j < 4; j++) {
            xout[c2 * XS + r4 + j] = fast_tanh(xout[c2 * XS + r4 + j] + a[2 * j] + b0);
            xout[(c2 + 1) * XS + r4 + j] =
                fast_tanh(xout[(c2 + 1) * XS + r4 + j] + a[2 * j + 1] + b1);
        }
    }
}

// agg = adj @ h -> WORK0 [d][r] stride XS. 512 threads:
// d4=(t&15)*4, rg=((t>>4)&3)*4, wq=t>>6 (0..7). h streamed in 8x32-row chunks.
__device__ void stage_agg(float* sm, int t, const float* __restrict__ adjb,
                          const float* __restrict__ hb, int bcast) {
    const int d4 = (t & 15) * 4;
    const int rg = ((t >> 4) & 3) * 4;
    const int wq = t >> 6;
    float4 acc[4];
    acc[0] = acc[1] = acc[2] = acc[3] = make_float4(0.f, 0.f, 0.f, 0.f);
    if (bcast) {
        float4 h4 = *(const float4*)(hb + d4);
#pragma unroll
        for (int i = 0; i < 2; i++) {
            int idx = t + i * NTHR;
            *(float4*)(sm + idx * 4) = *(const float4*)(adjb + idx * 4);
        }
        __syncthreads();
#pragma unroll 4
        for (int w = 0; w < 32; w++) {
            int wa = wq * 32 + w;
#pragma unroll
            for (int rr = 0; rr < 4; rr++) {
                float a = sm[(rg + rr) * NV + wa];
                acc[rr].x += a * h4.x; acc[rr].y += a * h4.y;
                acc[rr].z += a * h4.z; acc[rr].w += a * h4.w;
            }
        }
    } else {
        float* hbuf = sm + WORK1;
        float4 p0 = *(const float4*)(hb + t * 4);
#pragma unroll
        for (int i = 0; i < 2; i++) {
            int idx = t + i * NTHR;
            *(float4*)(sm + idx * 4) = *(const float4*)(adjb + idx * 4);
        }
        *(float4*)(hbuf + t * 4) = p0;
#pragma unroll 2
        for (int c = 0; c < 8; c++) {
            float4 q0;
            if (c < 7) q0 = *(const float4*)(hb + (c + 1) * 2048 + t * 4);
            __syncthreads();
            const float* hc = hbuf + (c & 1) * 2048;
#pragma unroll
            for (int j = 0; j < 4; j++) {
                int wl = wq * 4 + j;
                float4 h4 = *(const float4*)(hc + wl * 64 + d4);
                int wa = c * 32 + wl;
#pragma unroll
                for (int rr = 0; rr < 4; rr++) {
                    float a = sm[(rg + rr) * NV + wa];
                    acc[rr].x += a * h4.x; acc[rr].y += a * h4.y;
                    acc[rr].z += a * h4.z; acc[rr].w += a * h4.w;
                }
            }
            if (c < 7) *(float4*)(hbuf + ((c + 1) & 1) * 2048 + t * 4) = q0;
        }
        __syncthreads();
    }
    float* pb = sm + WORK1;
    if (wq < 4) {
#pragma unroll
        for (int rr = 0; rr < 4; rr++)
            *(float4*)(pb + wq * 1024 + (rg + rr) * ND + d4) = acc[rr];
    }
    __syncthreads();
    if (wq >= 4) {
#pragma unroll
        for (int rr = 0; rr < 4; rr++) {
            float4* p = (float4*)(pb + (wq - 4) * 1024 + (rg + rr) * ND + d4);
            float4 v = *p;
            v.x += acc[rr].x; v.y += acc[rr].y; v.z += acc[rr].z; v.w += acc[rr].w;
            *p = v;
        }
    }
    __syncthreads();
#pragma unroll
    for (int i = 0; i < 2; i++) {
        int idx = t + i * NTHR;
        int r = idx >> 6, d = idx & 63;
        float s = pb[d + r * ND] + pb[1024 + d + r * ND] +
                  pb[2048 + d + r * ND] + pb[3072 + d + r * ND];
        sm[WORK0 + d * XS + r] = s;
    }
    __syncthreads();
}

__device__ void euler_step(float* sm, int t, const float* __restrict__ adjb,
                           const float* __restrict__ hb, int bcast, int v0,
                           const float* __restrict__ bin, const float* __restrict__ bh0,
                           const float* __restrict__ bh1, const float* __restrict__ bout,
                           float* __restrict__ out1, float* __restrict__ out2) {
    const int c2 = (t & 31) * 2;
    const int r2 = ((t >> 5) & 7) * 2;
    const int kk = t >> 8;
    float2 hpA, hpB;
    if (kk == 1) {
        if (bcast) {
            hpA = *(const float2*)(hb + c2);
            hpB = hpA;
        } else {
            hpA = *(const float2*)(hb + (v0 + r2) * ND + c2);
            hpB = *(const float2*)(hb + (v0 + r2 + 1) * ND + c2);
        }
    }
    stage_agg(sm, t, adjb, hb, bcast);
    float* xA = sm + WORK0;
    float* xB = sm + WORK1;
    layer128<ND>(t, sm + W_IN, bin, xA, xB);
    __syncthreads();
    layer128<NH>(t, sm + W_H0, bh0, xB, xA);
    __syncthreads();
    layer128<NH>(t, sm + W_H1, bh1, xA, xB);
    __syncthreads();
    // final 128->64: 2r x 2c, k-split; partials in WORK0 (stride 17 pad)
    {
        float a[4] = {0.f, 0.f, 0.f, 0.f};
        const float* xp = xB + kk * 64 * XS + r2;
        const float* wp = sm + W_OUT + kk * 64 * ND + c2;
#pragma unroll 4
        for (int k = 0; k < 64; k++) {
            float2 xv = *(const float2*)xp;
            float2 wv = *(const float2*)wp;
            xp += XS; wp += ND;
            a[0] += xv.x * wv.x; a[1] += xv.x * wv.y;
            a[2] += xv.y * wv.x; a[3] += xv.y * wv.y;
        }
        float* p = sm + WORK0;
        if (kk == 0) {
#pragma unroll
            for (int rr = 0; rr < 2; rr++) {
                p[(c2 + 0) * 17 + r2 + rr] = a[rr * 2 + 0];
                p[(c2 + 1) * 17 + r2 + rr] = a[rr * 2 + 1];
            }
        }
        __syncthreads();
        if (kk == 1) {
            float b0 = __ldg(bout + c2), b1 = __ldg(bout + c2 + 1);
#pragma unroll
            for (int rr = 0; rr < 2; rr++) {
                float d0 = p[(c2 + 0) * 17 + r2 + rr] + a[rr * 2 + 0] + b0;
                float d1 = p[(c2 + 1) * 17 + r2 + rr] + a[rr * 2 + 1] + b1;
                float2 hp = (rr == 0) ? hpA : hpB;
                float2 o;
                o.x = hp.x + 0.25f * fast_tanh(d0);
                o.y = hp.y + 0.25f * fast_tanh(d1);
                *(float2*)(out1 + (v0 + r2 + rr) * ND + c2) = o;
                if (out2) *(float2*)(out2 + (v0 + r2 + rr) * ND + c2) = o;
            }
        }
    }
}

__device__ void gru_step(float* sm, int t, const float* __restrict__ adjb,
                         const float* __restrict__ hb, int v0,
                         const float* __restrict__ vrow, const float* __restrict__ mrowg,
                         const float* __restrict__ br, const float* __restrict__ bz,
                         const float* __restrict__ bg, const float* __restrict__ bo,
                         float* __restrict__ post, float* __restrict__ xp) {
    float* aggT = sm + WORK0;
    float* h1T = sm + WORK0 + 64 * XS;
    float* xT = sm + WORK0 + 128 * XS;
    float* mrow = sm + WORK0 + 160 * XS;
    float* rT = sm + WORK1;
    float* zT = sm + WORK1 + 64 * XS;

    float h1pf[2], xv1;
#pragma unroll
    for (int i = 0; i < 2; i++) {
        int idx = t + i * NTHR;
        h1pf[i] = hb[(v0 + (idx >> 6)) * ND + (idx & 63)];
    }
    {
        int r = t >> 5, c = t & 31;
        xv1 = vrow[(v0 + r) * NI + c] * mrowg[(v0 + r) * NI + c];
    }
    stage_agg(sm, t, adjb, hb, 0);
#pragma unroll
    for (int i = 0; i < 2; i++) {
        int idx = t + i * NTHR;
        h1T[(idx & 63) * XS + (idx >> 6)] = h1pf[i];
    }
    {
        int r = t >> 5, c = t & 31;
        xT[c * XS + r] = xv1;
    }
    if (t < ROWS) {
        float s = 0.f;
        for (int c = 0; c < NI; c++) s += fabsf(mrowg[(v0 + t) * NI + c]);
        mrow[t] = (s > 1e-4f) ? 1.0f : 0.0f;
    }
    __syncthreads();

    const int c2 = (t & 31) * 2;
    const int r2 = ((t >> 5) & 7) * 2;
    if (t < 256) {
        float br0 = __ldg(br + c2), br1 = __ldg(br + c2 + 1);
        float bz0 = __ldg(bz + c2), bz1 = __ldg(bz + c2 + 1);
        float ar00 = 0.f, ar01 = 0.f, ar10 = 0.f, ar11 = 0.f;
        float az00 = 0.f, az01 = 0.f, az10 = 0.f, az11 = 0.f;
        const float* wr = sm + G_WR + c2;
        const float* wz = sm + G_WZ + c2;
        const float* xq = xT + r2;
#pragma unroll 4
        for (int k = 0; k < NI; k++) {
            float2 xv = *(const float2*)xq;
            float2 wrv = *(const float2*)wr;
            float2 wzv = *(const float2*)wz;
            xq += XS; wr += ND; wz += ND;
            ar00 += xv.x * wrv.x; ar01 += xv.x * wrv.y;
            ar10 += xv.y * wrv.x; ar11 += xv.y * wrv.y;
            az00 += xv.x * wzv.x; az01 += xv.x * wzv.y;
            az10 += xv.y * wzv.x; az11 += xv.y * wzv.y;
        }
        const float* xa = aggT + r2;
#pragma unroll 4
        for (int k = 0; k < ND; k++) {
            float2 xv = *(const float2*)xa;
            float2 wrv = *(const float2*)wr;
            float2 wzv = *(const float2*)wz;
            xa += XS; wr += ND; wz += ND;
            ar00 += xv.x * wrv.x; ar01 += xv.x * wrv.y;
            ar10 += xv.y * wrv.x; ar11 += xv.y * wrv.y;
            az00 += xv.x * wzv.x; az01 += xv.x * wzv.y;
            az10 += xv.y * wzv.x; az11 += xv.y * wzv.y;
        }
        rT[c2 * XS + r2 + 0] = fast_sig(ar00 + br0);
        rT[c2 * XS + r2 + 1] = fast_sig(ar10 + br0);
        rT[(c2 + 1) * XS + r2 + 0] = fast_sig(ar01 + br1);
        rT[(c2 + 1) * XS + r2 + 1] = fast_sig(ar11 + br1);
        zT[c2 * XS + r2 + 0] = fast_sig(az00 + bz0);
        zT[c2 * XS + r2 + 1] = fast_sig(az10 + bz0);
        zT[(c2 + 1) * XS + r2 + 0] = fast_sig(az01 + bz1);
        zT[(c2 + 1) * XS + r2 + 1] = fast_sig(az11 + bz1);
    }
    __syncthreads();
#pragma unroll
    for (int i = 0; i < 2; i++) {
        int idx = t + i * NTHR;
        int r = idx >> 6, d = idx & 63;
        rT[d * XS + r] *= aggT[d * XS + r];
    }
    __syncthreads();
    if (t < 256) {
        float bg0 = __ldg(bg + c2), bg1 = __ldg(bg + c2 + 1);
        float ag00 = 0.f, ag01 = 0.f, ag10 = 0.f, ag11 = 0.f;
        const float* wg = sm + G_WG + c2;
        const float* xq = xT + r2;
#pragma unroll 4
        for (int k = 0; k < NI; k++) {
            float2 xv = *(const float2*)xq;
            float2 wgv = *(const float2*)wg;
            xq += XS; wg += ND;
            ag00 += xv.x * wgv.x; ag01 += xv.x * wgv.y;
            ag10 += xv.y * wgv.x; ag11 += xv.y * wgv.y;
        }
        const float* xr = rT + r2;
#pragma unroll 4
        for (int k = 0; k < ND; k++) {
            float2 xv = *(const float2*)xr;
            float2 wgv = *(const float2*)wg;
            xr += XS; wg += ND;
            ag00 += xv.x * wgv.x; ag01 += xv.x * wgv.y;
            ag10 += xv.y * wgv.x; ag11 += xv.y * wgv.y;
        }
#pragma unroll
        for (int rr = 0; rr < 2; rr++) {
            int r = r2 + rr;
            float m = mrow[r];
            float g0 = fast_tanh(((rr == 0) ? ag00 : ag10) + bg0);
            float g1 = fast_tanh(((rr == 0) ? ag01 : ag11) + bg1);
            float z0 = zT[c2 * XS + r], z1 = zT[(c2 + 1) * XS + r];
            float h0v = h1T[c2 * XS + r], h1v = h1T[(c2 + 1) * XS + r];
            float n0 = (1.f - z0) * h0v + z0 * g0;
            float n1 = (1.f - z1) * h1v + z1 * g1;
            float2 o;
            o.x = h0v + m * (n0 - h0v);
            o.y = h1v + m * (n1 - h1v);
            *(float2*)(post + (v0 + r) * ND + c2) = o;
        }
    }
    if (xp && t < 256) {
        const int cx = (t & 15) * 2;
        const int r = t >> 4;
        float a0 = 0.f, a1 = 0.f;
        const float* wo = sm + G_WO + cx;
        const float* hq = h1T + r;
#pragma unroll 4
        for (int k = 0; k < ND; k++) {
            float hv = *hq;
            float2 w = *(const float2*)wo;
            hq += XS; wo += NI;
            a0 += hv * w.x; a1 += hv * w.y;
        }
        float2 o;
        o.x = a0 + __ldg(bo + cx);
        o.y = a1 + __ldg(bo + cx + 1);
        *(float2*)(xp + (v0 + r) * NI + cx) = o;
    }
}

__global__ void init_kernel(float* __restrict__ trj) {
    int i = threadIdx.x;
    if (i < 197) trj[i] = 0.25f * (float)i;
}

__global__ void __launch_bounds__(NTHR, 1) __cluster_dims__(CLUSTER, 1, 1)
node_persist(
    const float* __restrict__ values, const float* __restrict__ masks,
    const float* __restrict__ adj, const float* __restrict__ h0,
    const float* __restrict__ Wo_g, const float* __restrict__ bo,
    const float* __restrict__ Win_g, const float* __restrict__ bin,
    const float* __restrict__ Wh_g, const float* __restrict__ bh,
    const float* __restrict__ Wode_g, const float* __restrict__ bode,
    const float* __restrict__ Wr_g, const float* __restrict__ br,
    const float* __restrict__ Wz_g, const float* __restrict__ bz,
    const float* __restrict__ Wg_g, const float* __restrict__ bg,
    float* __restrict__ XP, float* __restrict__ PRE,
    float* __restrict__ PREN, float* __restrict__ POST) {
    extern __shared__ __align__(16) float sm[];
    const int t = threadIdx.x;
    const int b = blockIdx.x >> 4;
    const int v0 = (blockIdx.x & 15) * ROWS;
    const float* adjb = adj + ((long long)b * NV + v0) * NV;
    const long long SL = (long long)NV * ND;
    float* PREb = PRE + (long long)b * 197 * SL;
    float* PRENb = PREN + (long long)b * NT * SL;
    float* POSTb = POST + (long long)b * NT * SL;
    float* XPb = XP + (long long)b * 49 * NV * NI;
    const float* valb = values + (long long)b * NT * NV * NI;
    const float* mskb = masks + (long long)b * NT * NV * NI;

    smcopy(sm + W_IN, Win_g, 8192, t);
    smcopy(sm + W_H0, Wh_g, 16384, t);
    smcopy(sm + W_H1, Wh_g + 16384, 16384, t);
    smcopy(sm + W_OUT, Wode_g, 8192, t);
    __syncthreads();

    euler_step(sm, t, adjb, h0, 1, v0, bin, bh, bh + NH, bode, PREb, PRENb);
    cluster_barrier();

    for (int tt = 0; tt < NT; tt++) {
        smcopy(sm + G_WR, Wr_g, 6144, t);
        smcopy(sm + G_WZ, Wz_g, 6144, t);
        smcopy(sm + G_WG, Wg_g, 6144, t);
        smcopy(sm + G_WO, Wo_g, 2048, t);
        __syncthreads();
        gru_step(sm, t, adjb, PRENb + (long long)tt * SL, v0,
                 valb + (long long)tt * NV * NI, mskb + (long long)tt * NV * NI,
                 br, bz, bg, bo, POSTb + (long long)tt * SL,
                 tt ? (XPb + (long long)(tt - 1) * NV * NI) : nullptr);
        cluster_barrier();
        if (tt < NT - 1) {
            smcopy(sm + W_H0, Wh_g, 16384, t);
            smcopy(sm + W_H1, Wh_g + 16384, 16384, t);
            __syncthreads();
            const float* hin = POSTb + (long long)tt * SL;
#pragma unroll 1
            for (int k = 0; k < 4; k++) {
                float* o1 = PREb + (long long)(1 + 4 * tt + k) * SL;
                float* o2 = (k == 3) ? (PRENb + (long long)(tt + 1) * SL) : nullptr;
                euler_step(sm, t, adjb, hin, 0, v0, bin, bh, bh + NH, bode, o1, o2);
                cluster_barrier();
                hin = o1;
            }
        }
    }
}

extern "C" void kernel_launch(void* const* d_in, const int* in_sizes, int n_in,
                              void* d_out, int out_size) {
    const float* values = (const float*)d_in[0];
    const float* masks  = (const float*)d_in[1];
    const float* adj    = (const float*)d_in[2];
    const float* h0     = (const float*)d_in[3];
    const float* W_out  = (const float*)d_in[4];
    const float* b_out  = (const float*)d_in[5];
    const float* Win    = (const float*)d_in[6];
    const float* bin    = (const float*)d_in[7];
    const float* Wh     = (const float*)d_in[8];
    const float* bh     = (const float*)d_in[9];
    const float* Wode   = (const float*)d_in[10];
    const float* bode   = (const float*)d_in[11];
    const float* Wr     = (const float*)d_in[12];
    const float* br     = (const float*)d_in[13];
    const float* Wz     = (const float*)d_in[14];
    const float* bz     = (const float*)d_in[15];
    const float* Wg     = (const float*)d_in[16];
    const float* bg     = (const float*)d_in[17];

    float* out = (float*)d_out;
    float* XP   = out;
    float* PRE  = XP + (long long)NB * 49 * NV * NI;
    float* PREN = PRE + (long long)NB * 197 * NV * ND;
    float* POST = PREN + (long long)NB * NT * NV * ND;
    float* TRJ  = POST + (long long)NB * NT * NV * ND;

    const size_t smbytes = SM_FLOATS * sizeof(float);
    static int configured = 0;
    if (!configured) {
        cudaFuncSetAttribute(node_persist,
                             cudaFuncAttributeNonPortableClusterSizeAllowed, 1);
        cudaFuncSetAttribute(node_persist,
                             cudaFuncAttributeMaxDynamicSharedMemorySize, (int)smbytes);
        configured = 1;
    }

    init_kernel<<<1, 256>>>(TRJ);
    node_persist<<<GRID, NTHR, smbytes>>>(values, masks, adj, h0, W_out, b_out,
                                          Win, bin, Wh, bh, Wode, bode,
                                          Wr, br, Wz, bz, Wg, bg,
                                          XP, PRE, PREN, POST);
}